// round 1
// baseline (speedup 1.0000x reference)
#include <cuda_runtime.h>
#include <cuda_bf16.h>
#include <math.h>

// Problem constants (fixed by the reference)
#define T_TOK 2048          // B*S tokens
#define HDIM  2048
#define FDIM  5504
#define EEXP  8
#define KTOP  2

// GEMM tiling
#define TM 128
#define TN 64
#define TK 16

// ---------------- scratch (static device arrays; no allocation) ----------------
__device__ int   g_cnt[EEXP];
__device__ int   g_pair_tok[EEXP * T_TOK];
__device__ float g_pair_w[EEXP * T_TOK];
// fixed-stride per-expert intermediate: hbuf[(e*T + slot)*F + f]  (~361 MB)
__device__ float g_hbuf[(size_t)EEXP * T_TOK * FDIM];

// ---------------- kernel 0: zero counters ----------------
__global__ void zero_cnt_kernel() {
    if (threadIdx.x < EEXP) g_cnt[threadIdx.x] = 0;
}

// ---------------- kernel 1: router logits + top-2 softmax + bucketing ----------------
// grid = T_TOK blocks, 256 threads (8 warps; warp e computes logit for expert e)
__global__ void __launch_bounds__(256) router_kernel(const float* __restrict__ x,
                                                     const float* __restrict__ rw) {
    int t = blockIdx.x;
    int warp = threadIdx.x >> 5;
    int lane = threadIdx.x & 31;
    __shared__ float logits[EEXP];

    const float* xr = x + (size_t)t * HDIM;
    const float* wr = rw + (size_t)warp * HDIM;
    float s = 0.f;
    for (int h = lane * 4; h < HDIM; h += 32 * 4) {
        float4 xv = *(const float4*)(xr + h);
        float4 wv = *(const float4*)(wr + h);
        s = fmaf(xv.x, wv.x, s);
        s = fmaf(xv.y, wv.y, s);
        s = fmaf(xv.z, wv.z, s);
        s = fmaf(xv.w, wv.w, s);
    }
    #pragma unroll
    for (int o = 16; o; o >>= 1) s += __shfl_down_sync(0xffffffffu, s, o);
    if (lane == 0) logits[warp] = s;
    __syncthreads();

    if (threadIdx.x == 0) {
        // top-1 (ties -> lowest index, matching jax.lax.top_k)
        int i0 = 0; float v0 = logits[0];
        #pragma unroll
        for (int i = 1; i < EEXP; i++) {
            if (logits[i] > v0) { v0 = logits[i]; i0 = i; }
        }
        // top-2
        int i1 = -1; float v1 = -3.0e38f;
        #pragma unroll
        for (int i = 0; i < EEXP; i++) {
            if (i == i0) continue;
            if (logits[i] > v1) { v1 = logits[i]; i1 = i; }
        }
        // softmax over the two selected logits
        float e1 = expf(v1 - v0);
        float inv = 1.f / (1.f + e1);
        float p0 = inv;
        float p1 = e1 * inv;

        int s0 = atomicAdd(&g_cnt[i0], 1);
        g_pair_tok[i0 * T_TOK + s0] = t;
        g_pair_w  [i0 * T_TOK + s0] = p0;
        int s1 = atomicAdd(&g_cnt[i1], 1);
        g_pair_tok[i1 * T_TOK + s1] = t;
        g_pair_w  [i1 * T_TOK + s1] = p1;
    }
}

// ---------------- kernel 2: grouped gate/up GEMM + SiLU ----------------
// grid = (FDIM/TN=86, T_TOK/TM=16, EEXP=8), 256 threads.
// Computes g = Xe @ Wg^T, u = Xe @ Wu^T for this expert's token rows,
// writes silu(g)*u into g_hbuf.
__global__ void __launch_bounds__(256) gateup_kernel(const float* __restrict__ x,
                                                     const float* __restrict__ gw,
                                                     const float* __restrict__ uw) {
    int e = blockIdx.z;
    int cntE = g_cnt[e];
    int m0 = blockIdx.y * TM;
    if (m0 >= cntE) return;
    int n0 = blockIdx.x * TN;

    __shared__ float As[TK][TM];
    __shared__ float Bg[TK][TN];
    __shared__ float Bu[TK][TN];
    __shared__ int   toks[TM];

    int tid = threadIdx.x;
    if (tid < TM) {
        int r = m0 + tid;
        toks[tid] = (r < cntE) ? g_pair_tok[e * T_TOK + r] : -1;
    }
    __syncthreads();

    int tx = tid & 15;       // 0..15 -> 4 cols each
    int ty = tid >> 4;       // 0..15 -> 8 rows each

    float acc_g[8][4];
    float acc_u[8][4];
    #pragma unroll
    for (int i = 0; i < 8; i++)
        #pragma unroll
        for (int j = 0; j < 4; j++) { acc_g[i][j] = 0.f; acc_u[i][j] = 0.f; }

    const float* gwB = gw + ((size_t)e * FDIM + n0) * HDIM;
    const float* uwB = uw + ((size_t)e * FDIM + n0) * HDIM;

    for (int k0 = 0; k0 < HDIM; k0 += TK) {
        // A tile: 128 rows x 16 k = 512 float4 (2 per thread), stored K-major
        #pragma unroll
        for (int i = 0; i < 2; i++) {
            int v = tid + i * 256;
            int row = v >> 2;
            int c4  = v & 3;
            int tok = toks[row];
            float4 val = make_float4(0.f, 0.f, 0.f, 0.f);
            if (tok >= 0) val = *(const float4*)(x + (size_t)tok * HDIM + k0 + c4 * 4);
            As[c4 * 4 + 0][row] = val.x;
            As[c4 * 4 + 1][row] = val.y;
            As[c4 * 4 + 2][row] = val.z;
            As[c4 * 4 + 3][row] = val.w;
        }
        // B tiles: 64 rows x 16 k = 256 float4 each (1 per thread)
        {
            int row = tid >> 2;
            int c4  = tid & 3;
            float4 gv = *(const float4*)(gwB + (size_t)row * HDIM + k0 + c4 * 4);
            Bg[c4 * 4 + 0][row] = gv.x;
            Bg[c4 * 4 + 1][row] = gv.y;
            Bg[c4 * 4 + 2][row] = gv.z;
            Bg[c4 * 4 + 3][row] = gv.w;
            float4 uv = *(const float4*)(uwB + (size_t)row * HDIM + k0 + c4 * 4);
            Bu[c4 * 4 + 0][row] = uv.x;
            Bu[c4 * 4 + 1][row] = uv.y;
            Bu[c4 * 4 + 2][row] = uv.z;
            Bu[c4 * 4 + 3][row] = uv.w;
        }
        __syncthreads();

        #pragma unroll
        for (int kk = 0; kk < TK; kk++) {
            float a[8], bg[4], bu[4];
            *(float4*)&a[0] = *(const float4*)&As[kk][ty * 8];
            *(float4*)&a[4] = *(const float4*)&As[kk][ty * 8 + 4];
            *(float4*)&bg[0] = *(const float4*)&Bg[kk][tx * 4];
            *(float4*)&bu[0] = *(const float4*)&Bu[kk][tx * 4];
            #pragma unroll
            for (int i = 0; i < 8; i++) {
                #pragma unroll
                for (int j = 0; j < 4; j++) {
                    acc_g[i][j] = fmaf(a[i], bg[j], acc_g[i][j]);
                    acc_u[i][j] = fmaf(a[i], bu[j], acc_u[i][j]);
                }
            }
        }
        __syncthreads();
    }

    // epilogue: silu(g)*u -> hbuf
    #pragma unroll
    for (int i = 0; i < 8; i++) {
        int row = m0 + ty * 8 + i;
        if (row < cntE) {
            size_t base = ((size_t)e * T_TOK + row) * FDIM + n0 + tx * 4;
            #pragma unroll
            for (int j = 0; j < 4; j++) {
                float g = acc_g[i][j];
                float u = acc_u[i][j];
                float h = (g / (1.f + expf(-g))) * u;   // silu(g)*u
                g_hbuf[base + j] = h;
            }
        }
    }
}

// ---------------- kernel 3: grouped down GEMM + weighted scatter ----------------
// grid = (HDIM/TN=32, T_TOK/TM=16, EEXP=8), 256 threads.
__global__ void __launch_bounds__(256) down_kernel(const float* __restrict__ dw,
                                                   float* __restrict__ out) {
    int e = blockIdx.z;
    int cntE = g_cnt[e];
    int m0 = blockIdx.y * TM;
    if (m0 >= cntE) return;
    int n0 = blockIdx.x * TN;

    __shared__ float As[TK][TM];
    __shared__ float Bd[TK][TN];

    int tid = threadIdx.x;
    int tx = tid & 15;
    int ty = tid >> 4;

    float acc[8][4];
    #pragma unroll
    for (int i = 0; i < 8; i++)
        #pragma unroll
        for (int j = 0; j < 4; j++) acc[i][j] = 0.f;

    const float* dwB = dw + ((size_t)e * HDIM + n0) * FDIM;
    const float* aB  = g_hbuf + (size_t)(e * T_TOK + m0) * FDIM;

    for (int k0 = 0; k0 < FDIM; k0 += TK) {
        #pragma unroll
        for (int i = 0; i < 2; i++) {
            int v = tid + i * 256;
            int row = v >> 2;
            int c4  = v & 3;
            float4 val = make_float4(0.f, 0.f, 0.f, 0.f);
            if (m0 + row < cntE)
                val = *(const float4*)(aB + (size_t)row * FDIM + k0 + c4 * 4);
            As[c4 * 4 + 0][row] = val.x;
            As[c4 * 4 + 1][row] = val.y;
            As[c4 * 4 + 2][row] = val.z;
            As[c4 * 4 + 3][row] = val.w;
        }
        {
            int row = tid >> 2;
            int c4  = tid & 3;
            float4 dv = *(const float4*)(dwB + (size_t)row * FDIM + k0 + c4 * 4);
            Bd[c4 * 4 + 0][row] = dv.x;
            Bd[c4 * 4 + 1][row] = dv.y;
            Bd[c4 * 4 + 2][row] = dv.z;
            Bd[c4 * 4 + 3][row] = dv.w;
        }
        __syncthreads();

        #pragma unroll
        for (int kk = 0; kk < TK; kk++) {
            float a[8], b[4];
            *(float4*)&a[0] = *(const float4*)&As[kk][ty * 8];
            *(float4*)&a[4] = *(const float4*)&As[kk][ty * 8 + 4];
            *(float4*)&b[0] = *(const float4*)&Bd[kk][tx * 4];
            #pragma unroll
            for (int i = 0; i < 8; i++)
                #pragma unroll
                for (int j = 0; j < 4; j++)
                    acc[i][j] = fmaf(a[i], b[j], acc[i][j]);
        }
        __syncthreads();
    }

    // weighted scatter-add into output (exactly 2 commutative adds per element)
    #pragma unroll
    for (int i = 0; i < 8; i++) {
        int row = m0 + ty * 8 + i;
        if (row < cntE) {
            int tok = g_pair_tok[e * T_TOK + row];
            float w = g_pair_w[e * T_TOK + row];
            float* orow = out + (size_t)tok * HDIM + n0 + tx * 4;
            #pragma unroll
            for (int j = 0; j < 4; j++)
                atomicAdd(&orow[j], acc[i][j] * w);
        }
    }
}

// ---------------- launch ----------------
extern "C" void kernel_launch(void* const* d_in, const int* in_sizes, int n_in,
                              void* d_out, int out_size) {
    const float* x  = (const float*)d_in[0];   // [B,S,H]
    const float* rw = (const float*)d_in[1];   // [E,H]
    const float* gw = (const float*)d_in[2];   // [E,F,H]
    const float* uw = (const float*)d_in[3];   // [E,F,H]
    const float* dw = (const float*)d_in[4];   // [E,H,F]
    float* out = (float*)d_out;                // [B,S,H]

    cudaMemsetAsync(out, 0, (size_t)out_size * sizeof(float));
    zero_cnt_kernel<<<1, 32>>>();
    router_kernel<<<T_TOK, 256>>>(x, rw);
    gateup_kernel<<<dim3(FDIM / TN, T_TOK / TM, EEXP), 256>>>(x, gw, uw);
    down_kernel<<<dim3(HDIM / TN, T_TOK / TM, EEXP), 256>>>(dw, out);
}